// round 1
// baseline (speedup 1.0000x reference)
#include <cuda_runtime.h>

#define NN   3072
#define INF  512
#define NH   8
#define HD   64
#define OF   512   // NH*HD
#define MW   96    // NN/32 mask words per row

// ---------------- scratch (no allocations allowed) ----------------
__device__ float     g_h[NN * OF];        // node features after GEMM  [n][h*64+d]
__device__ float     g_P[NH * NN];        // exp(s)      [h][n]
__device__ float     g_p[NH * NN];        // exp(0.2 s)  [h][n]
__device__ float     g_Q[NH * NN];        // exp(t)      [h][n]
__device__ float     g_q[NH * NN];        // exp(0.2 t)  [h][n]
__device__ unsigned  g_mask[NN * MW];     // adjacency (+diag) bitmask

// ---------------- Kernel 1: g_h = X @ W^T (SGEMM) ----------------
// X [3072,512] row-major, W [512,512] row-major (out,in). BM=128 BN=64 BK=16.
__global__ __launch_bounds__(256) void gemm_kernel(const float* __restrict__ X,
                                                   const float* __restrict__ Wm) {
    __shared__ float As[16][132];
    __shared__ float Bs[16][68];
    const int tid = threadIdx.x;
    const int bm = blockIdx.x * 128;
    const int bn = blockIdx.y * 64;
    const int ty = tid >> 4;        // 0..15 (row group of 8)
    const int tx = tid & 15;        // 0..15 (col group of 4)
    const int a_row = tid >> 1;     // 0..127
    const int a_k4  = (tid & 1) * 2;
    const int b_row = tid >> 2;     // 0..63
    const int b_k4  = tid & 3;

    float acc[8][4];
#pragma unroll
    for (int i = 0; i < 8; i++)
#pragma unroll
        for (int j = 0; j < 4; j++) acc[i][j] = 0.f;

    for (int k0 = 0; k0 < INF; k0 += 16) {
        const float4* Ap = (const float4*)(X  + (size_t)(bm + a_row) * INF + k0);
        float4 av0 = Ap[a_k4];
        float4 av1 = Ap[a_k4 + 1];
        const float4* Bp = (const float4*)(Wm + (size_t)(bn + b_row) * INF + k0);
        float4 bv = Bp[b_k4];

        __syncthreads();
        As[a_k4*4+0][a_row] = av0.x; As[a_k4*4+1][a_row] = av0.y;
        As[a_k4*4+2][a_row] = av0.z; As[a_k4*4+3][a_row] = av0.w;
        As[a_k4*4+4][a_row] = av1.x; As[a_k4*4+5][a_row] = av1.y;
        As[a_k4*4+6][a_row] = av1.z; As[a_k4*4+7][a_row] = av1.w;
        Bs[b_k4*4+0][b_row] = bv.x;  Bs[b_k4*4+1][b_row] = bv.y;
        Bs[b_k4*4+2][b_row] = bv.z;  Bs[b_k4*4+3][b_row] = bv.w;
        __syncthreads();

#pragma unroll
        for (int k = 0; k < 16; k++) {
            float4 ar0 = *(const float4*)&As[k][ty * 8];
            float4 ar1 = *(const float4*)&As[k][ty * 8 + 4];
            float4 br  = *(const float4*)&Bs[k][tx * 4];
            float am[8] = {ar0.x, ar0.y, ar0.z, ar0.w, ar1.x, ar1.y, ar1.z, ar1.w};
            float bb[4] = {br.x, br.y, br.z, br.w};
#pragma unroll
            for (int i = 0; i < 8; i++)
#pragma unroll
                for (int j = 0; j < 4; j++) acc[i][j] += am[i] * bb[j];
        }
    }
#pragma unroll
    for (int i = 0; i < 8; i++) {
        float4 v = make_float4(acc[i][0], acc[i][1], acc[i][2], acc[i][3]);
        *(float4*)(g_h + (size_t)(bm + ty * 8 + i) * OF + bn + tx * 4) = v;
    }
}

// ---------------- Kernel 2: per-(node,head) exp coefficients ----------------
__global__ void coef_kernel(const float* __restrict__ a_src,
                            const float* __restrict__ a_dst) {
    int idx = blockIdx.x * blockDim.x + threadIdx.x;   // idx = h*NN + n
    int h = idx / NN;
    int n = idx % NN;
    const float4* hv = (const float4*)(g_h + (size_t)n * OF + h * HD);
    const float4* as = (const float4*)(a_src + h * HD);
    const float4* ad = (const float4*)(a_dst + h * HD);
    float s = 0.f, t = 0.f;
#pragma unroll
    for (int k = 0; k < 16; k++) {
        float4 hh = hv[k], va = as[k], vd = ad[k];
        s += hh.x * va.x + hh.y * va.y + hh.z * va.z + hh.w * va.w;
        t += hh.x * vd.x + hh.y * vd.y + hh.z * vd.z + hh.w * vd.w;
    }
    g_P[idx] = __expf(s);
    g_p[idx] = __expf(0.2f * s);
    g_Q[idx] = __expf(t);
    g_q[idx] = __expf(0.2f * t);
}

// ---------------- Kernel 3: pack adjacency (+ diagonal) into bitmask ----------------
__global__ void mask_kernel(const int* __restrict__ adj) {
    int warp = (blockIdx.x * blockDim.x + threadIdx.x) >> 5;
    int lane = threadIdx.x & 31;
    int i = warp / MW;
    int w = warp % MW;
    if (i >= NN) return;
    int col = w * 32 + lane;
    int v = adj[(size_t)i * NN + col];
    unsigned bits = __ballot_sync(0xffffffffu, (v != 0) || (col == i));
    if (lane == 0) g_mask[i * MW + w] = bits;
}

// ---------------- Kernel 4: fused masked softmax + aggregation ----------------
// CTA: TI=64 queries x 1 head. Thread owns 1 query x 16 d's.
// w_ij = max(P_i*Q_j, p_i*q_j)  ( == exp(leakyrelu(s_i+t_j)) ), masked; single pass.
#define TI 64
#define JT 32
__global__ __launch_bounds__(256) void attn_kernel(float* __restrict__ out) {
    __shared__ float    sh_h[JT][HD];   // 8KB j-tile of features (this head)
    __shared__ float    sh_Q[JT];
    __shared__ float    sh_q[JT];
    __shared__ unsigned sh_mw[TI];

    const int head = blockIdx.y;
    const int i0   = blockIdx.x * TI;
    const int t    = threadIdx.x;
    const int il   = t >> 2;           // 0..63 local query
    const int d0   = (t & 3) * 16;     // d segment
    const int i    = i0 + il;

    const float Pi = g_P[head * NN + i];
    const float pi = g_p[head * NN + i];

    float acc[16];
#pragma unroll
    for (int k = 0; k < 16; k++) acc[k] = 0.f;
    float Z = 0.f;

    for (int tile = 0; tile < NN / JT; tile++) {
        const int j0 = tile * JT;
        __syncthreads();
        // stage h tile: 2048 floats, 2 float4 per thread
        {
            const float4* src = (const float4*)(g_h + (size_t)j0 * OF + head * HD);
            int r = t >> 3;                 // tile row 0..31
            int c4 = (t & 7) * 2;           // f4 col 0..15
            float4 v0 = src[r * (OF / 4) + c4];
            float4 v1 = src[r * (OF / 4) + c4 + 1];
            float4* dst = ((float4*)sh_h) + t * 2;
            dst[0] = v0;
            dst[1] = v1;
        }
        if (t < JT)                sh_Q[t]            = g_Q[head * NN + j0 + t];
        else if (t < 2 * JT)       sh_q[t - JT]       = g_q[head * NN + j0 + t - JT];
        else if (t < 2 * JT + TI)  sh_mw[t - 2 * JT]  = g_mask[(size_t)(i0 + t - 2 * JT) * MW + tile];
        __syncthreads();

        const unsigned mw = sh_mw[il];
#pragma unroll 8
        for (int jj = 0; jj < JT; jj++) {
            float w = fmaxf(Pi * sh_Q[jj], pi * sh_q[jj]);
            w = ((mw >> jj) & 1u) ? w : 0.0f;
            Z += w;
            const float4* hv = (const float4*)(&sh_h[jj][d0]);
            float4 a0 = hv[0], a1 = hv[1], a2 = hv[2], a3 = hv[3];
            acc[0]  += w * a0.x;  acc[1]  += w * a0.y;  acc[2]  += w * a0.z;  acc[3]  += w * a0.w;
            acc[4]  += w * a1.x;  acc[5]  += w * a1.y;  acc[6]  += w * a1.z;  acc[7]  += w * a1.w;
            acc[8]  += w * a2.x;  acc[9]  += w * a2.y;  acc[10] += w * a2.z;  acc[11] += w * a2.w;
            acc[12] += w * a3.x;  acc[13] += w * a3.y;  acc[14] += w * a3.z;  acc[15] += w * a3.w;
        }
    }

    const float invZ = 1.0f / Z;   // Z>0: diagonal always in mask
    float* op = out + (size_t)i * OF + head * HD + d0;
#pragma unroll
    for (int k = 0; k < 16; k += 4) {
        float4 v = make_float4(acc[k] * invZ, acc[k + 1] * invZ,
                               acc[k + 2] * invZ, acc[k + 3] * invZ);
        *(float4*)(op + k) = v;
    }
}

// ---------------- launch ----------------
extern "C" void kernel_launch(void* const* d_in, const int* in_sizes, int n_in,
                              void* d_out, int out_size) {
    const float* x     = (const float*)d_in[0];
    const int*   adj   = (const int*)d_in[1];
    const float* W     = (const float*)d_in[2];
    const float* a_src = (const float*)d_in[3];
    const float* a_dst = (const float*)d_in[4];
    float* out = (float*)d_out;

    gemm_kernel<<<dim3(NN / 128, OF / 64), 256>>>(x, W);
    coef_kernel<<<(NH * NN) / 256, 256>>>(a_src, a_dst);
    mask_kernel<<<(NN * MW * 32) / 256, 256>>>(adj);
    attn_kernel<<<dim3(NN / TI, NH), 256>>>(out);
}

// round 2
// speedup vs baseline: 2.8221x; 2.8221x over previous
#include <cuda_runtime.h>

#define NN   3072
#define INF  512
#define NH   8
#define HD   64
#define OF   512   // NH*HD
#define MW   96    // NN/32 mask words per row

// ---------------- scratch (no allocations allowed) ----------------
__device__ float     g_h[NN * OF];        // node features after GEMM  [n][h*64+d]
__device__ float     g_P[NH * NN];        // exp(s)      [h][n]
__device__ float     g_p[NH * NN];        // exp(0.2 s)  [h][n]
__device__ float     g_Q[NH * NN];        // exp(t)      [h][n]
__device__ float     g_q[NH * NN];        // exp(0.2 t)  [h][n]
__device__ unsigned  g_maskT[MW * NN];    // adjacency (+diag) bitmask, TRANSPOSED: [word][node]

// ---------------- Kernel 1: g_h = X @ W^T (SGEMM) ----------------
__global__ __launch_bounds__(256) void gemm_kernel(const float* __restrict__ X,
                                                   const float* __restrict__ Wm) {
    __shared__ float As[16][132];
    __shared__ float Bs[16][68];
    const int tid = threadIdx.x;
    const int bm = blockIdx.x * 128;
    const int bn = blockIdx.y * 64;
    const int ty = tid >> 4;
    const int tx = tid & 15;
    const int a_row = tid >> 1;
    const int a_k4  = (tid & 1) * 2;
    const int b_row = tid >> 2;
    const int b_k4  = tid & 3;

    float acc[8][4];
#pragma unroll
    for (int i = 0; i < 8; i++)
#pragma unroll
        for (int j = 0; j < 4; j++) acc[i][j] = 0.f;

    for (int k0 = 0; k0 < INF; k0 += 16) {
        const float4* Ap = (const float4*)(X  + (size_t)(bm + a_row) * INF + k0);
        float4 av0 = Ap[a_k4];
        float4 av1 = Ap[a_k4 + 1];
        const float4* Bp = (const float4*)(Wm + (size_t)(bn + b_row) * INF + k0);
        float4 bv = Bp[b_k4];

        __syncthreads();
        As[a_k4*4+0][a_row] = av0.x; As[a_k4*4+1][a_row] = av0.y;
        As[a_k4*4+2][a_row] = av0.z; As[a_k4*4+3][a_row] = av0.w;
        As[a_k4*4+4][a_row] = av1.x; As[a_k4*4+5][a_row] = av1.y;
        As[a_k4*4+6][a_row] = av1.z; As[a_k4*4+7][a_row] = av1.w;
        Bs[b_k4*4+0][b_row] = bv.x;  Bs[b_k4*4+1][b_row] = bv.y;
        Bs[b_k4*4+2][b_row] = bv.z;  Bs[b_k4*4+3][b_row] = bv.w;
        __syncthreads();

#pragma unroll
        for (int k = 0; k < 16; k++) {
            float4 ar0 = *(const float4*)&As[k][ty * 8];
            float4 ar1 = *(const float4*)&As[k][ty * 8 + 4];
            float4 br  = *(const float4*)&Bs[k][tx * 4];
            float am[8] = {ar0.x, ar0.y, ar0.z, ar0.w, ar1.x, ar1.y, ar1.z, ar1.w};
            float bb[4] = {br.x, br.y, br.z, br.w};
#pragma unroll
            for (int i = 0; i < 8; i++)
#pragma unroll
                for (int j = 0; j < 4; j++) acc[i][j] += am[i] * bb[j];
        }
    }
#pragma unroll
    for (int i = 0; i < 8; i++) {
        float4 v = make_float4(acc[i][0], acc[i][1], acc[i][2], acc[i][3]);
        *(float4*)(g_h + (size_t)(bm + ty * 8 + i) * OF + bn + tx * 4) = v;
    }
}

// ---------------- Kernel 2: per-(node,head) exp coefficients ----------------
__global__ void coef_kernel(const float* __restrict__ a_src,
                            const float* __restrict__ a_dst) {
    int idx = blockIdx.x * blockDim.x + threadIdx.x;   // idx = h*NN + n
    int h = idx / NN;
    int n = idx % NN;
    const float4* hv = (const float4*)(g_h + (size_t)n * OF + h * HD);
    const float4* as = (const float4*)(a_src + h * HD);
    const float4* ad = (const float4*)(a_dst + h * HD);
    float s = 0.f, t = 0.f;
#pragma unroll
    for (int k = 0; k < 16; k++) {
        float4 hh = hv[k], va = as[k], vd = ad[k];
        s += hh.x * va.x + hh.y * va.y + hh.z * va.z + hh.w * va.w;
        t += hh.x * vd.x + hh.y * vd.y + hh.z * vd.z + hh.w * vd.w;
    }
    g_P[idx] = __expf(s);
    g_p[idx] = __expf(0.2f * s);
    g_Q[idx] = __expf(t);
    g_q[idx] = __expf(0.2f * t);
}

// ---------------- Kernel 3: pack adjacency (+ diagonal) into TRANSPOSED bitmask ----------------
__global__ void mask_kernel(const int* __restrict__ adj) {
    int warp = (blockIdx.x * blockDim.x + threadIdx.x) >> 5;
    int lane = threadIdx.x & 31;
    int i = warp / MW;          // node (row of adj)
    int w = warp % MW;          // 32-col word
    if (i >= NN) return;
    int col = w * 32 + lane;
    int v = adj[(size_t)i * NN + col];
    unsigned bits = __ballot_sync(0xffffffffu, (v != 0) || (col == i));
    if (lane == 0) g_maskT[(size_t)w * NN + i] = bits;   // transposed
}

// ---------------- Kernel 4: fused masked softmax + aggregation ----------------
// CTA: TI=64 queries x 1 head, 256 threads. Per tile of JT=32 j's:
//   phase A: stage h tile into smem + generate w tile (w = exp(leakyrelu(s_i+t_j)) masked)
//   phase B: thread = 2 queries x 8 d's pure FFMA accumulation from smem.
// Conflict-free layout: each thread's 8-d slice = cols [dt*4, dt*4+4) and [32+dt*4, ...).
#define TI 64
#define JT 32
__global__ __launch_bounds__(256) void attn_kernel(float* __restrict__ out) {
    __shared__ __align__(16) float sh_h[JT][HD];   // 8KB
    __shared__ __align__(16) float sh_w[JT][TI];   // 8KB
    __shared__ float sh_P[TI];
    __shared__ float sh_p[TI];

    const int head = blockIdx.y;
    const int i0   = blockIdx.x * TI;
    const int t    = threadIdx.x;

    // stage/w-gen roles
    const int r   = t >> 3;         // j row within tile, 0..31
    const int cl  = (t & 7) * 4;    // h col segment base (and w i-segment base)

    // main-loop roles
    const int qg  = t >> 3;         // query group 0..31 (2 queries each)
    const int dt  = t & 7;          // d thread
    const int dA  = dt * 4;
    const int dB  = 32 + dt * 4;

    // preload P,p for this CTA's 64 queries
    if (t < TI) {
        sh_P[t] = g_P[head * NN + i0 + t];
        sh_p[t] = g_p[head * NN + i0 + t];
    }

    const float* hsrc_base = g_h + (size_t)r * OF + head * HD;
    const float* Qbase = g_Q + head * NN + r;
    const float* qbase = g_q + head * NN + r;

    // prefetch tile 0
    float4 hv0, hv1;
    uint4  m0, m1;
    float  Qj, qj;
    {
        const float4* s = (const float4*)(hsrc_base);
        hv0 = s[cl >> 2];
        hv1 = s[(cl >> 2) + 8];
        Qj = Qbase[0];
        qj = qbase[0];
        m0 = *(const uint4*)(g_maskT + i0 + cl);
        m1 = *(const uint4*)(g_maskT + i0 + 32 + cl);
    }

    float4 acc00 = make_float4(0.f,0.f,0.f,0.f);
    float4 acc01 = make_float4(0.f,0.f,0.f,0.f);
    float4 acc10 = make_float4(0.f,0.f,0.f,0.f);
    float4 acc11 = make_float4(0.f,0.f,0.f,0.f);
    float Z0 = 0.f, Z1 = 0.f;

    __syncthreads();   // sh_P/sh_p visible

    for (int tile = 0; tile < NN / JT; tile++) {
        // phase A: store staged h, generate w (reads only gmem regs + sh_P/p)
        *(float4*)&sh_h[r][cl]      = hv0;
        *(float4*)&sh_h[r][32 + cl] = hv1;
        {
            unsigned mm0[4] = {m0.x, m0.y, m0.z, m0.w};
            unsigned mm1[4] = {m1.x, m1.y, m1.z, m1.w};
            float wv0[4], wv1[4];
#pragma unroll
            for (int k = 0; k < 4; k++) {
                int ia = cl + k;
                int ib = 32 + cl + k;
                float wa = fmaxf(sh_P[ia] * Qj, sh_p[ia] * qj);
                float wb = fmaxf(sh_P[ib] * Qj, sh_p[ib] * qj);
                wv0[k] = ((mm0[k] >> r) & 1u) ? wa : 0.f;
                wv1[k] = ((mm1[k] >> r) & 1u) ? wb : 0.f;
            }
            *(float4*)&sh_w[r][cl]      = make_float4(wv0[0], wv0[1], wv0[2], wv0[3]);
            *(float4*)&sh_w[r][32 + cl] = make_float4(wv1[0], wv1[1], wv1[2], wv1[3]);
        }
        __syncthreads();

        // prefetch next tile while main loop runs
        if (tile + 1 < NN / JT) {
            const int nt = tile + 1;
            const float4* s = (const float4*)(hsrc_base + (size_t)nt * JT * OF);
            hv0 = s[cl >> 2];
            hv1 = s[(cl >> 2) + 8];
            Qj = Qbase[nt * JT];
            qj = qbase[nt * JT];
            m0 = *(const uint4*)(g_maskT + (size_t)nt * NN + i0 + cl);
            m1 = *(const uint4*)(g_maskT + (size_t)nt * NN + i0 + 32 + cl);
        }

        // phase B: accumulate
#pragma unroll 8
        for (int jj = 0; jj < JT; jj++) {
            float2 wv = *(const float2*)&sh_w[jj][qg * 2];
            float4 a0 = *(const float4*)&sh_h[jj][dA];
            float4 a1 = *(const float4*)&sh_h[jj][dB];
            Z0 += wv.x;
            Z1 += wv.y;
            acc00.x += wv.x * a0.x; acc00.y += wv.x * a0.y;
            acc00.z += wv.x * a0.z; acc00.w += wv.x * a0.w;
            acc01.x += wv.x * a1.x; acc01.y += wv.x * a1.y;
            acc01.z += wv.x * a1.z; acc01.w += wv.x * a1.w;
            acc10.x += wv.y * a0.x; acc10.y += wv.y * a0.y;
            acc10.z += wv.y * a0.z; acc10.w += wv.y * a0.w;
            acc11.x += wv.y * a1.x; acc11.y += wv.y * a1.y;
            acc11.z += wv.y * a1.z; acc11.w += wv.y * a1.w;
        }
        __syncthreads();   // protect sh_h/sh_w before next tile's phase A
    }

    const float iz0 = 1.0f / Z0;   // diagonal always in mask -> Z > 0
    const float iz1 = 1.0f / Z1;
    float* o0 = out + (size_t)(i0 + qg * 2) * OF + head * HD;
    float* o1 = o0 + OF;
    *(float4*)(o0 + dA) = make_float4(acc00.x * iz0, acc00.y * iz0, acc00.z * iz0, acc00.w * iz0);
    *(float4*)(o0 + dB) = make_float4(acc01.x * iz0, acc01.y * iz0, acc01.z * iz0, acc01.w * iz0);
    *(float4*)(o1 + dA) = make_float4(acc10.x * iz1, acc10.y * iz1, acc10.z * iz1, acc10.w * iz1);
    *(float4*)(o1 + dB) = make_float4(acc11.x * iz1, acc11.y * iz1, acc11.z * iz1, acc11.w * iz1);
}

// ---------------- launch ----------------
extern "C" void kernel_launch(void* const* d_in, const int* in_sizes, int n_in,
                              void* d_out, int out_size) {
    const float* x     = (const float*)d_in[0];
    const int*   adj   = (const int*)d_in[1];
    const float* W     = (const float*)d_in[2];
    const float* a_src = (const float*)d_in[3];
    const float* a_dst = (const float*)d_in[4];
    float* out = (float*)d_out;

    gemm_kernel<<<dim3(NN / 128, OF / 64), 256>>>(x, W);
    coef_kernel<<<(NH * NN) / 256, 256>>>(a_src, a_dst);
    mask_kernel<<<(NN * MW * 32) / 256, 256>>>(adj);
    attn_kernel<<<dim3(NN / TI, NH), 256>>>(out);
}

// round 4
// speedup vs baseline: 5.8731x; 2.0811x over previous
#include <cuda_runtime.h>
#include <cuda_bf16.h>
#include <cstdint>

#define NN   3072
#define INF  512
#define NH   8
#define HD   64
#define OF   512   // NH*HD
#define MW   96    // NN/32 mask words per row
#define KT   32    // j tile (one mask word)
#define MT   128   // i tile per CTA
#define NTILES (NN / KT)

// ---------------- scratch ----------------
__device__ float         g_h[NN * OF];
__device__ float         g_P[NH * NN];
__device__ float         g_p[NH * NN];
__device__ float         g_Q[NH * NN];
__device__ float         g_q[NH * NN];
__device__ unsigned      g_mask[NN * MW];            // row-major [i][jword]
__device__ __nv_bfloat16 g_hT1[NH * HD * NN];        // hi split, [h][d][n]
__device__ __nv_bfloat16 g_hT2[NH * HD * NN];        // lo split

__device__ __forceinline__ uint32_t smem_u32(const void* p) {
    uint32_t a;
    asm("{ .reg .u64 t; cvta.to.shared.u64 t, %1; cvt.u32.u64 %0, t; }" : "=r"(a) : "l"(p));
    return a;
}

__device__ __forceinline__ void mma_bf16(float* c, const uint32_t* a, uint32_t b0, uint32_t b1) {
    asm volatile(
        "mma.sync.aligned.m16n8k16.row.col.f32.bf16.bf16.f32 "
        "{%0,%1,%2,%3}, {%4,%5,%6,%7}, {%8,%9}, {%0,%1,%2,%3};"
        : "+f"(c[0]), "+f"(c[1]), "+f"(c[2]), "+f"(c[3])
        : "r"(a[0]), "r"(a[1]), "r"(a[2]), "r"(a[3]), "r"(b0), "r"(b1));
}

__device__ __forceinline__ void ldmx4(uint32_t* r, uint32_t addr) {
    asm volatile("ldmatrix.sync.aligned.m8n8.x4.shared.b16 {%0,%1,%2,%3}, [%4];"
                 : "=r"(r[0]), "=r"(r[1]), "=r"(r[2]), "=r"(r[3]) : "r"(addr));
}

// pack two fp32 -> bf16x2 (lo = w0, hi = w1) and residual pack
__device__ __forceinline__ void split2(float w0, float w1, uint32_t& hi, uint32_t& lo) {
    uint32_t h;
    asm("cvt.rn.bf16x2.f32 %0, %1, %2;" : "=r"(h) : "f"(w1), "f"(w0));
    float r0 = w0 - __uint_as_float(h << 16);
    float r1 = w1 - __uint_as_float(h & 0xffff0000u);
    uint32_t l;
    asm("cvt.rn.bf16x2.f32 %0, %1, %2;" : "=r"(l) : "f"(r1), "f"(r0));
    hi = h; lo = l;
}

// ---------------- Kernel 1: g_h = X @ W^T (SGEMM) ----------------
__global__ __launch_bounds__(256) void gemm_kernel(const float* __restrict__ X,
                                                   const float* __restrict__ Wm) {
    __shared__ float As[16][132];
    __shared__ float Bs[16][68];
    const int tid = threadIdx.x;
    const int bm = blockIdx.x * 128;
    const int bn = blockIdx.y * 64;
    const int ty = tid >> 4;
    const int tx = tid & 15;
    const int a_row = tid >> 1;
    const int a_k4  = (tid & 1) * 2;
    const int b_row = tid >> 2;
    const int b_k4  = tid & 3;

    float acc[8][4];
#pragma unroll
    for (int i = 0; i < 8; i++)
#pragma unroll
        for (int j = 0; j < 4; j++) acc[i][j] = 0.f;

    for (int k0 = 0; k0 < INF; k0 += 16) {
        const float4* Ap = (const float4*)(X  + (size_t)(bm + a_row) * INF + k0);
        float4 av0 = Ap[a_k4];
        float4 av1 = Ap[a_k4 + 1];
        const float4* Bp = (const float4*)(Wm + (size_t)(bn + b_row) * INF + k0);
        float4 bv = Bp[b_k4];

        __syncthreads();
        As[a_k4*4+0][a_row] = av0.x; As[a_k4*4+1][a_row] = av0.y;
        As[a_k4*4+2][a_row] = av0.z; As[a_k4*4+3][a_row] = av0.w;
        As[a_k4*4+4][a_row] = av1.x; As[a_k4*4+5][a_row] = av1.y;
        As[a_k4*4+6][a_row] = av1.z; As[a_k4*4+7][a_row] = av1.w;
        Bs[b_k4*4+0][b_row] = bv.x;  Bs[b_k4*4+1][b_row] = bv.y;
        Bs[b_k4*4+2][b_row] = bv.z;  Bs[b_k4*4+3][b_row] = bv.w;
        __syncthreads();

#pragma unroll
        for (int k = 0; k < 16; k++) {
            float4 ar0 = *(const float4*)&As[k][ty * 8];
            float4 ar1 = *(const float4*)&As[k][ty * 8 + 4];
            float4 br  = *(const float4*)&Bs[k][tx * 4];
            float am[8] = {ar0.x, ar0.y, ar0.z, ar0.w, ar1.x, ar1.y, ar1.z, ar1.w};
            float bb[4] = {br.x, br.y, br.z, br.w};
#pragma unroll
            for (int i = 0; i < 8; i++)
#pragma unroll
                for (int j = 0; j < 4; j++) acc[i][j] += am[i] * bb[j];
        }
    }
#pragma unroll
    for (int i = 0; i < 8; i++) {
        float4 v = make_float4(acc[i][0], acc[i][1], acc[i][2], acc[i][3]);
        *(float4*)(g_h + (size_t)(bm + ty * 8 + i) * OF + bn + tx * 4) = v;
    }
}

// ---------------- Kernel 2: per-(node,head) exp coefficients ----------------
__global__ void coef_kernel(const float* __restrict__ a_src,
                            const float* __restrict__ a_dst) {
    int idx = blockIdx.x * blockDim.x + threadIdx.x;   // h*NN + n
    int h = idx / NN;
    int n = idx % NN;
    const float4* hv = (const float4*)(g_h + (size_t)n * OF + h * HD);
    const float4* as = (const float4*)(a_src + h * HD);
    const float4* ad = (const float4*)(a_dst + h * HD);
    float s = 0.f, t = 0.f;
#pragma unroll
    for (int k = 0; k < 16; k++) {
        float4 hh = hv[k], va = as[k], vd = ad[k];
        s += hh.x * va.x + hh.y * va.y + hh.z * va.z + hh.w * va.w;
        t += hh.x * vd.x + hh.y * vd.y + hh.z * vd.z + hh.w * vd.w;
    }
    g_P[idx] = __expf(s);
    g_p[idx] = __expf(0.2f * s);
    g_Q[idx] = __expf(t);
    g_q[idx] = __expf(0.2f * t);
}

// ---------------- Kernel 3: adjacency (+diag) bitmask ----------------
__global__ void mask_kernel(const int* __restrict__ adj) {
    int warp = (blockIdx.x * blockDim.x + threadIdx.x) >> 5;
    int lane = threadIdx.x & 31;
    int i = warp / MW;
    int w = warp % MW;
    if (i >= NN) return;
    int col = w * 32 + lane;
    int v = adj[(size_t)i * NN + col];
    unsigned bits = __ballot_sync(0xffffffffu, (v != 0) || (col == i));
    if (lane == 0) g_mask[i * MW + w] = bits;
}

// ---------------- Kernel 3b: transpose + bf16 hi/lo split of h ----------------
__global__ __launch_bounds__(256) void hsplit_kernel() {
    __shared__ float tl[32][65];
    const int h  = blockIdx.y;
    const int n0 = blockIdx.x * 32;
    const int t  = threadIdx.x;
    {
        int r  = t >> 3;
        int c8 = (t & 7) * 8;
        const float* src = g_h + (size_t)(n0 + r) * OF + h * HD + c8;
        float4 v0 = *(const float4*)src;
        float4 v1 = *(const float4*)(src + 4);
        tl[r][c8+0] = v0.x; tl[r][c8+1] = v0.y; tl[r][c8+2] = v0.z; tl[r][c8+3] = v0.w;
        tl[r][c8+4] = v1.x; tl[r][c8+5] = v1.y; tl[r][c8+6] = v1.z; tl[r][c8+7] = v1.w;
    }
    __syncthreads();
    const int d  = t >> 2;
    const int ns = (t & 3) * 8;
    uint32_t hi[4], lo[4];
#pragma unroll
    for (int k = 0; k < 4; k++) {
        float va = tl[ns + 2*k][d];
        float vb = tl[ns + 2*k + 1][d];
        split2(va, vb, hi[k], lo[k]);
    }
    size_t o = (size_t)(h * HD + d) * NN + n0 + ns;
    *(uint4*)(g_hT1 + o) = make_uint4(hi[0], hi[1], hi[2], hi[3]);
    *(uint4*)(g_hT2 + o) = make_uint4(lo[0], lo[1], lo[2], lo[3]);
}

// ---------------- Kernel 4: HMMA masked softmax-aggregate ----------------
// CTA = 128 i x 1 head, 8 warps, warp = 16 i x 64 d.
// A (w, bf16 split) generated directly in fragment registers; B (h split) staged
// in swizzled smem, ldmatrix.x4; 3 mma products accumulate; Z in registers.
__global__ __launch_bounds__(256) void attn_kernel(float* __restrict__ out) {
    // B smem: [buf][split][d*64B], 16B chunk index xor-swizzled by (d>>1)&3
    __shared__ __align__(16) unsigned char Bsm[2][2][HD * 64];
    __shared__ __align__(8)  float2 QQ[2][KT];

    const int tid  = threadIdx.x;
    const int w    = tid >> 5;
    const int L    = tid & 31;
    const int head = blockIdx.y;
    const int i0   = blockIdx.x * MT;

    // B staging role
    const int sd   = tid >> 2;        // d row 0..63
    const int sseg = tid & 3;         // 16B chunk
    const __nv_bfloat16* h1p = g_hT1 + (size_t)(head * HD + sd) * NN;
    const __nv_bfloat16* h2p = g_hT2 + (size_t)(head * HD + sd) * NN;
    const uint32_t soff = (uint32_t)(sd * 64 + ((sseg ^ ((sd >> 1) & 3)) << 4));

    // attention role
    const int r  = L >> 2;            // fragment row 0..7
    const int cb = (L & 3) * 2;       // fragment col base
    const int irow0 = i0 + w * 16 + r;
    const int irow1 = irow0 + 8;
    const float P0 = g_P[head * NN + irow0];
    const float p0 = g_p[head * NN + irow0];
    const float P1 = g_P[head * NN + irow1];
    const float p1 = g_p[head * NN + irow1];
    const unsigned* mrow0 = g_mask + (size_t)irow0 * MW;
    const unsigned* mrow1 = g_mask + (size_t)irow1 * MW;

    const uint32_t b1base = smem_u32(&Bsm[0][0][0]);

    float acc[8][4];
#pragma unroll
    for (int n = 0; n < 8; n++)
#pragma unroll
        for (int k = 0; k < 4; k++) acc[n][k] = 0.f;
    float z0 = 0.f, z1 = 0.f;

    // prefetch tile 0
    uint4 nb1 = *(const uint4*)(h1p + sseg * 8);
    uint4 nb2 = *(const uint4*)(h2p + sseg * 8);
    unsigned nm0 = mrow0[0];
    unsigned nm1 = mrow1[0];
    float nQ = 0.f, nq = 0.f;
    if (tid < KT) {
        nQ = g_Q[head * NN + tid];
        nq = g_q[head * NN + tid];
    }

    for (int t = 0; t < NTILES; t++) {
        const int buf = t & 1;
        // store staged tile
        *(uint4*)&Bsm[buf][0][soff] = nb1;
        *(uint4*)&Bsm[buf][1][soff] = nb2;
        if (tid < KT) QQ[buf][tid] = make_float2(nQ, nq);
        const unsigned mw0 = nm0;
        const unsigned mw1 = nm1;
        __syncthreads();

        // prefetch next tile
        if (t + 1 < NTILES) {
            const int j0 = (t + 1) * KT;
            nb1 = *(const uint4*)(h1p + j0 + sseg * 8);
            nb2 = *(const uint4*)(h2p + j0 + sseg * 8);
            nm0 = mrow0[t + 1];
            nm1 = mrow1[t + 1];
            if (tid < KT) {
                nQ = g_Q[head * NN + j0 + tid];
                nq = g_q[head * NN + j0 + tid];
            }
        }

        // ---- generate A fragments (w, bf16 hi/lo split) in registers ----
        uint32_t A1[2][4], A2[2][4];   // [kstep][areg]
#pragma unroll
        for (int ks = 0; ks < 2; ks++) {
            const int jb = cb + ks * 16;
            float2 q0 = QQ[buf][jb];
            float2 q1 = QQ[buf][jb + 1];
            float2 q2 = QQ[buf][jb + 8];
            float2 q3 = QQ[buf][jb + 9];
            // row0 (irow0): a0 (k=jb,jb+1), a2 (k=jb+8,jb+9)
            float w00 = fmaxf(P0 * q0.x, p0 * q0.y); w00 = ((mw0 >> jb)       & 1u) ? w00 : 0.f;
            float w01 = fmaxf(P0 * q1.x, p0 * q1.y); w01 = ((mw0 >> (jb + 1)) & 1u) ? w01 : 0.f;
            float w02 = fmaxf(P0 * q2.x, p0 * q2.y); w02 = ((mw0 >> (jb + 8)) & 1u) ? w02 : 0.f;
            float w03 = fmaxf(P0 * q3.x, p0 * q3.y); w03 = ((mw0 >> (jb + 9)) & 1u) ? w03 : 0.f;
            // row1 (irow1): a1, a3
            float w10 = fmaxf(P1 * q0.x, p1 * q0.y); w10 = ((mw1 >> jb)       & 1u) ? w10 : 0.f;
            float w11 = fmaxf(P1 * q1.x, p1 * q1.y); w11 = ((mw1 >> (jb + 1)) & 1u) ? w11 : 0.f;
            float w12 = fmaxf(P1 * q2.x, p1 * q2.y); w12 = ((mw1 >> (jb + 8)) & 1u) ? w12 : 0.f;
            float w13 = fmaxf(P1 * q3.x, p1 * q3.y); w13 = ((mw1 >> (jb + 9)) & 1u) ? w13 : 0.f;
            z0 += (w00 + w01) + (w02 + w03);
            z1 += (w10 + w11) + (w12 + w13);
            split2(w00, w01, A1[ks][0], A2[ks][0]);
            split2(w10, w11, A1[ks][1], A2[ks][1]);
            split2(w02, w03, A1[ks][2], A2[ks][2]);
            split2(w12, w13, A1[ks][3], A2[ks][3]);
        }

        // ---- B ldmatrix + MMA per n-tile ----
        const uint32_t bufofs = (uint32_t)buf * (2 * HD * 64);
        const int ld_d = (L & 7);          // row within 8-row matrix
        const int ld_m = (L >> 3);         // matrix index = j group 0..3
#pragma unroll
        for (int nt = 0; nt < 8; nt++) {
            const int d = nt * 8 + ld_d;
            const uint32_t addr1 = b1base + bufofs + (uint32_t)(d * 64 + ((ld_m ^ ((d >> 1) & 3)) << 4));
            const uint32_t addr2 = addr1 + (uint32_t)(HD * 64);
            uint32_t B1[4], B2[4];
            ldmx4(B1, addr1);
            ldmx4(B2, addr2);
            mma_bf16(acc[nt], A1[0], B1[0], B1[1]);   // w1*h1 kstep0
            mma_bf16(acc[nt], A1[1], B1[2], B1[3]);   // w1*h1 kstep1
            mma_bf16(acc[nt], A1[0], B2[0], B2[1]);   // w1*h2 kstep0
            mma_bf16(acc[nt], A1[1], B2[2], B2[3]);   // w1*h2 kstep1
            mma_bf16(acc[nt], A2[0], B1[0], B1[1]);   // w2*h1 kstep0
            mma_bf16(acc[nt], A2[1], B1[2], B1[3]);   // w2*h1 kstep1
        }
    }

    // Z reduction across the 4 lanes sharing a fragment row
    z0 += __shfl_xor_sync(0xffffffffu, z0, 1);
    z0 += __shfl_xor_sync(0xffffffffu, z0, 2);
    z1 += __shfl_xor_sync(0xffffffffu, z1, 1);
    z1 += __shfl_xor_sync(0xffffffffu, z1, 2);
    const float iz0 = 1.0f / z0;   // diagonal always in mask -> Z > 0
    const float iz1 = 1.0f / z1;

    float* o0 = out + (size_t)irow0 * OF + head * HD + cb;
    float* o1 = out + (size_t)irow1 * OF + head * HD + cb;
#pragma unroll
    for (int nt = 0; nt < 8; nt++) {
        *(float2*)(o0 + nt * 8) = make_float2(acc[nt][0] * iz0, acc[nt][1] * iz0);
        *(float2*)(o1 + nt * 8) = make_float2(acc[nt][2] * iz1, acc[nt][3] * iz1);
    }
}

// ---------------- launch ----------------
extern "C" void kernel_launch(void* const* d_in, const int* in_sizes, int n_in,
                              void* d_out, int out_size) {
    const float* x     = (const float*)d_in[0];
    const int*   adj   = (const int*)d_in[1];
    const float* W     = (const float*)d_in[2];
    const float* a_src = (const float*)d_in[3];
    const float* a_dst = (const float*)d_in[4];
    float* out = (float*)d_out;

    gemm_kernel<<<dim3(NN / 128, OF / 64), 256>>>(x, W);
    coef_kernel<<<(NH * NN) / 256, 256>>>(a_src, a_dst);
    hsplit_kernel<<<dim3(NN / 32, NH), 256>>>();
    mask_kernel<<<(NN * MW * 32) / 256, 256>>>(adj);
    attn_kernel<<<dim3(NN / MT, NH), 256>>>(out);
}